// round 5
// baseline (speedup 1.0000x reference)
#include <cuda_runtime.h>
#include <cuda_bf16.h>

// Problem dims (fixed by dataset)
#define BB 4
#define TT_ 512
#define UU 128
#define DD 512
#define VV 512
#define GRID 128        // CTAs in main kernel; 512 tiles / 128 = 4 tiles each
#define NTILES 512      // 64 bt-blocks x 8 v-strips, tile = 32bt x 64v

// text projection scratch: tp[b*U+u][v] = text@W^T + bias   (1 MB, L2-resident)
__device__ float g_tp[BB * UU * VV];

// ---------------------------------------------------------------------------
// Kernel 1: tp[m, v] = sum_d text[m, d] * W[v, d] + bias[v]
// 32x32 tiles, 128 threads, grid (16,16). Also writes the length tail.
// ---------------------------------------------------------------------------
__global__ __launch_bounds__(128)
void tp_kernel(const float* __restrict__ text,
               const float* __restrict__ Wm,
               const float* __restrict__ bias,
               const int* __restrict__ slen,
               const int* __restrict__ tlen,
               float* __restrict__ out)
{
    __shared__ float As[16][36];
    __shared__ float Ws[16][36];

    const int tid = threadIdx.x;
    const int n0 = blockIdx.x * 32;
    const int m0 = blockIdx.y * 32;

    const float* Ap = text + (size_t)m0 * DD;
    const float* Wp = Wm   + (size_t)n0 * DD;

    const int r = tid >> 2;      // 0..31
    const int c = tid & 3;       // 0..3
    const int tx = tid & 7;      // cols tx*4 .. +3
    const int ty = tid >> 3;     // rows ty*2, ty*2+1

    float acc[2][4] = {};

    for (int k0 = 0; k0 < DD; k0 += 16) {
        float4 a = *(const float4*)(Ap + (size_t)r * DD + k0 + c * 4);
        float4 w = *(const float4*)(Wp + (size_t)r * DD + k0 + c * 4);
        __syncthreads();
        As[c*4+0][r] = a.x; As[c*4+1][r] = a.y; As[c*4+2][r] = a.z; As[c*4+3][r] = a.w;
        Ws[c*4+0][r] = w.x; Ws[c*4+1][r] = w.y; Ws[c*4+2][r] = w.z; Ws[c*4+3][r] = w.w;
        __syncthreads();
#pragma unroll
        for (int kk = 0; kk < 16; kk++) {
            float2 av = *(const float2*)&As[kk][ty * 2];
            float4 wv = *(const float4*)&Ws[kk][tx * 4];
            acc[0][0] += av.x * wv.x; acc[0][1] += av.x * wv.y;
            acc[0][2] += av.x * wv.z; acc[0][3] += av.x * wv.w;
            acc[1][0] += av.y * wv.x; acc[1][1] += av.y * wv.y;
            acc[1][2] += av.y * wv.z; acc[1][3] += av.y * wv.w;
        }
    }

    float4 bv = *(const float4*)(bias + n0 + tx * 4);
#pragma unroll
    for (int rr = 0; rr < 2; rr++) {
        float4 o;
        o.x = acc[rr][0] + bv.x; o.y = acc[rr][1] + bv.y;
        o.z = acc[rr][2] + bv.z; o.w = acc[rr][3] + bv.w;
        *(float4*)(g_tp + (size_t)(m0 + ty * 2 + rr) * VV + n0 + tx * 4) = o;
    }

    if (blockIdx.x == 0 && blockIdx.y == 0 && tid < 8) {
        size_t base = (size_t)BB * TT_ * UU * VV;
        if (tid < 4) out[base + tid] = (float)slen[tid];
        else         out[base + tid] = (float)tlen[tid - 4];
    }
}

// ---------------------------------------------------------------------------
// Kernel 2: software-pipelined fused kernel. grid=128 x 256 threads.
// Per CTA: 4 tiles (t = bid + 128*i). Pipeline:
//   GEMM(t0) -> sp_s[0]
//   for i in 0..2:  drain(t_i) INTERLEAVED with GEMM(t_{i+1}) -> sp_s[i+1 & 1]
//   drain(t3)
// Each GEMM k-chunk (of 32) carries 4 drain u-iterations (4*32 = 128 = UU).
// ---------------------------------------------------------------------------
__global__ __launch_bounds__(256, 1)
void sp_add_pipe(const float* __restrict__ speech,
                 const float* __restrict__ Wm,
                 float* __restrict__ out)
{
    __shared__ float As[16][36];        // A chunk [k][m]
    __shared__ float Ws[16][68];        // W chunk [k][n]
    __shared__ float sp_s[2][32][68];   // double-buffered sp tile (padded rows)

    const int tid = threadIdx.x;
    const int bid = blockIdx.x;

    const int lr = tid >> 2;   // gemm load row
    const int lc = tid & 3;    // gemm load k-subchunk
    const int tx = tid & 15;   // micro-tile col group / drain v4
    const int ty = tid >> 4;   // micro-tile row group / drain row

    float acc[2][4];

    // ================= prologue: GEMM(t0) -> sp_s[0] =================
    {
        const int t   = bid;
        const int v0  = (t & 7) * 64;
        const int bt0 = (t >> 3) * 32;
        const float* Ap = speech + (size_t)bt0 * DD;
        const float* Wp = Wm     + (size_t)v0 * DD;

#pragma unroll
        for (int i = 0; i < 2; i++)
#pragma unroll
            for (int j = 0; j < 4; j++) acc[i][j] = 0.f;

        float4 wreg = *(const float4*)(Wp + (size_t)lr * DD + lc * 4);
        float4 areg = make_float4(0.f, 0.f, 0.f, 0.f);
        if (tid < 128) areg = *(const float4*)(Ap + (size_t)lr * DD + lc * 4);

        for (int kc = 0; kc < 32; kc++) {
            __syncthreads();
            Ws[lc*4+0][lr] = wreg.x; Ws[lc*4+1][lr] = wreg.y;
            Ws[lc*4+2][lr] = wreg.z; Ws[lc*4+3][lr] = wreg.w;
            if (tid < 128) {
                As[lc*4+0][lr] = areg.x; As[lc*4+1][lr] = areg.y;
                As[lc*4+2][lr] = areg.z; As[lc*4+3][lr] = areg.w;
            }
            __syncthreads();
            if (kc < 31) {
                const int k0 = (kc + 1) * 16;
                wreg = *(const float4*)(Wp + (size_t)lr * DD + k0 + lc * 4);
                if (tid < 128)
                    areg = *(const float4*)(Ap + (size_t)lr * DD + k0 + lc * 4);
            }
#pragma unroll
            for (int kk = 0; kk < 16; kk++) {
                float2 av = *(const float2*)&As[kk][ty * 2];
                float4 wv = *(const float4*)&Ws[kk][tx * 4];
                acc[0][0] += av.x * wv.x; acc[0][1] += av.x * wv.y;
                acc[0][2] += av.x * wv.z; acc[0][3] += av.x * wv.w;
                acc[1][0] += av.y * wv.x; acc[1][1] += av.y * wv.y;
                acc[1][2] += av.y * wv.z; acc[1][3] += av.y * wv.w;
            }
        }
        *(float4*)&sp_s[0][ty*2    ][tx*4] =
            make_float4(acc[0][0], acc[0][1], acc[0][2], acc[0][3]);
        *(float4*)&sp_s[0][ty*2 + 1][tx*4] =
            make_float4(acc[1][0], acc[1][1], acc[1][2], acc[1][3]);
    }
    __syncthreads();

    // ================= pipelined body =================
    int buf  = 0;
    int tcur = bid;                       // tile held in sp_s[buf]
    for (int tn = bid + GRID; tn < NTILES; tn += GRID) {
        // ---- drain setup for tcur ----
        const int dv0  = (tcur & 7) * 64;
        const int dbt0 = (tcur >> 3) * 32;
        const int db   = dbt0 >> 9;

        const float4 s0 = *(const float4*)&sp_s[buf][ty     ][tx * 4];
        const float4 s1 = *(const float4*)&sp_s[buf][ty + 16][tx * 4];
        const float4* tpp = (const float4*)(g_tp + (size_t)db * UU * VV + dv0) + tx;
        float4* p0 = (float4*)out + (size_t)(dbt0 + ty) * UU * (VV/4) + (dv0 >> 2) + tx;
        float4* p1 = p0 + (size_t)16 * UU * (VV/4);

        // ---- gemm setup for tn ----
        const int v0  = (tn & 7) * 64;
        const int bt0 = (tn >> 3) * 32;
        const float* Ap = speech + (size_t)bt0 * DD;
        const float* Wp = Wm     + (size_t)v0 * DD;

#pragma unroll
        for (int i = 0; i < 2; i++)
#pragma unroll
            for (int j = 0; j < 4; j++) acc[i][j] = 0.f;

        float4 wreg = *(const float4*)(Wp + (size_t)lr * DD + lc * 4);
        float4 areg = make_float4(0.f, 0.f, 0.f, 0.f);
        if (tid < 128) areg = *(const float4*)(Ap + (size_t)lr * DD + lc * 4);

        for (int kc = 0; kc < 32; kc++) {
            __syncthreads();
            Ws[lc*4+0][lr] = wreg.x; Ws[lc*4+1][lr] = wreg.y;
            Ws[lc*4+2][lr] = wreg.z; Ws[lc*4+3][lr] = wreg.w;
            if (tid < 128) {
                As[lc*4+0][lr] = areg.x; As[lc*4+1][lr] = areg.y;
                As[lc*4+2][lr] = areg.z; As[lc*4+3][lr] = areg.w;
            }
            __syncthreads();
            if (kc < 31) {
                const int k0 = (kc + 1) * 16;
                wreg = *(const float4*)(Wp + (size_t)lr * DD + k0 + lc * 4);
                if (tid < 128)
                    areg = *(const float4*)(Ap + (size_t)lr * DD + k0 + lc * 4);
            }
            // ---- 4 drain u-iterations (u = kc*4 .. kc*4+3) ----
#pragma unroll
            for (int j = 0; j < 4; j++) {
                float4 tv = __ldg(tpp); tpp += VV / 4;
                float4 r0, r1;
                r0.x = s0.x + tv.x; r0.y = s0.y + tv.y;
                r0.z = s0.z + tv.z; r0.w = s0.w + tv.w;
                r1.x = s1.x + tv.x; r1.y = s1.y + tv.y;
                r1.z = s1.z + tv.z; r1.w = s1.w + tv.w;
                __stcs(p0, r0); p0 += VV / 4;
                __stcs(p1, r1); p1 += VV / 4;
            }
            // ---- 16 kk FFMAs ----
#pragma unroll
            for (int kk = 0; kk < 16; kk++) {
                float2 av = *(const float2*)&As[kk][ty * 2];
                float4 wv = *(const float4*)&Ws[kk][tx * 4];
                acc[0][0] += av.x * wv.x; acc[0][1] += av.x * wv.y;
                acc[0][2] += av.x * wv.z; acc[0][3] += av.x * wv.w;
                acc[1][0] += av.y * wv.x; acc[1][1] += av.y * wv.y;
                acc[1][2] += av.y * wv.z; acc[1][3] += av.y * wv.w;
            }
        }

        buf ^= 1;
        *(float4*)&sp_s[buf][ty*2    ][tx*4] =
            make_float4(acc[0][0], acc[0][1], acc[0][2], acc[0][3]);
        *(float4*)&sp_s[buf][ty*2 + 1][tx*4] =
            make_float4(acc[1][0], acc[1][1], acc[1][2], acc[1][3]);
        __syncthreads();
        tcur = tn;
    }

    // ================= epilogue: plain drain of last tile =================
    {
        const int dv0  = (tcur & 7) * 64;
        const int dbt0 = (tcur >> 3) * 32;
        const int db   = dbt0 >> 9;

        const float4 s0 = *(const float4*)&sp_s[buf][ty     ][tx * 4];
        const float4 s1 = *(const float4*)&sp_s[buf][ty + 16][tx * 4];
        const float4* tpp = (const float4*)(g_tp + (size_t)db * UU * VV + dv0) + tx;
        float4* p0 = (float4*)out + (size_t)(dbt0 + ty) * UU * (VV/4) + (dv0 >> 2) + tx;
        float4* p1 = p0 + (size_t)16 * UU * (VV/4);

#pragma unroll 4
        for (int u = 0; u < UU; u++) {
            float4 tv = __ldg(tpp); tpp += VV / 4;
            float4 r0, r1;
            r0.x = s0.x + tv.x; r0.y = s0.y + tv.y;
            r0.z = s0.z + tv.z; r0.w = s0.w + tv.w;
            r1.x = s1.x + tv.x; r1.y = s1.y + tv.y;
            r1.z = s1.z + tv.z; r1.w = s1.w + tv.w;
            __stcs(p0, r0); p0 += VV / 4;
            __stcs(p1, r1); p1 += VV / 4;
        }
    }
}

extern "C" void kernel_launch(void* const* d_in, const int* in_sizes, int n_in,
                              void* d_out, int out_size)
{
    const float* speech = (const float*)d_in[0];
    const float* text   = (const float*)d_in[1];
    const float* Wm     = (const float*)d_in[2];
    const float* bias   = (const float*)d_in[3];
    const int*   slen   = (const int*)d_in[4];
    const int*   tlen   = (const int*)d_in[5];

    // Phase 1: text projection (+ bias) into g_tp, plus length tail
    tp_kernel<<<dim3(16, 16), 128>>>(text, Wm, bias, slen, tlen, (float*)d_out);

    // Phase 2: pipelined fused speech projection + broadcast add
    sp_add_pipe<<<GRID, 256>>>(speech, Wm, (float*)d_out);
}

// round 6
// speedup vs baseline: 1.2183x; 1.2183x over previous
#include <cuda_runtime.h>
#include <cuda_bf16.h>

// Problem dims (fixed by dataset)
#define BB 4
#define TT_ 512
#define UU 128
#define DD 512
#define VV 512
#define MS (BB * TT_)   // 2048 speech rows
#define MT (BB * UU)    // 512 text rows

// Scratch: projected speech / text (both L2-resident, 126 MB L2)
__device__ float g_sp[MS * VV];   // speech @ W^T          (4 MB)
__device__ float g_tp[MT * VV];   // text @ W^T + bias     (1 MB)

typedef unsigned long long ull;

// Packed fp32x2 helpers (sm_103a)
#define PACK2(d, s) \
    asm("mov.b64 %0, {%1, %1};" : "=l"(d) : "r"(__float_as_uint(s)))
#define FMA2(acc, a, b) \
    asm("fma.rn.f32x2 %0, %1, %2, %0;" : "+l"(acc) : "l"(a), "l"(b))
#define ADD2(acc, b) \
    asm("add.rn.f32x2 %0, %0, %1;" : "+l"(acc) : "l"(b))

// ---------------------------------------------------------------------------
// Kernel 1: joint GEMM.  C[m, v] = sum_d A[m, d] * W[v, d]  (+bias for text)
// Tiles 64x64, BK=16, 256 threads, grid (8, 40):
//   by in [0,32): speech -> g_sp.   by in [32,40): text -> g_tp (bias added).
// Per-thread micro-tile 4x4 computed as 4x2 f32x2 accumulators (FFMA2).
// Also writes the float-cast length tail (block (0,0)).
// ---------------------------------------------------------------------------
__global__ __launch_bounds__(256, 4)
void joint_gemm_kernel(const float* __restrict__ speech,
                       const float* __restrict__ text,
                       const float* __restrict__ Wm,
                       const float* __restrict__ bias,
                       const int* __restrict__ slen,
                       const int* __restrict__ tlen,
                       float* __restrict__ out)
{
    __shared__ __align__(16) float As[16][68];   // [k][m], 272B row stride (16B mult)
    __shared__ __align__(16) float Ws[16][68];   // [k][n]

    const int tid = threadIdx.x;
    const int by  = blockIdx.y;
    const int n0  = blockIdx.x * 64;

    const float* A;
    float* C;
    const bool is_text = (by >= 32);
    if (!is_text) {
        A = speech + (size_t)by * 64 * DD;
        C = g_sp   + (size_t)by * 64 * VV;
    } else {
        A = text + (size_t)(by - 32) * 64 * DD;
        C = g_tp + (size_t)(by - 32) * 64 * VV;
    }

    const int lr = tid >> 2;     // 0..63  load row
    const int lc = tid & 3;      // 0..3   load k-subchunk
    const int tx = tid & 15;     // cols tx*4 .. +3
    const int ty = tid >> 4;     // rows ty*4 .. +3

    ull acc[4][2];
#pragma unroll
    for (int i = 0; i < 4; i++) { acc[i][0] = 0ull; acc[i][1] = 0ull; }

    const float* Arow = A  + (size_t)lr * DD + lc * 4;
    const float* Wrow = Wm + (size_t)(n0 + lr) * DD + lc * 4;

    float4 apre = *(const float4*)Arow;
    float4 wpre = *(const float4*)Wrow;

    for (int k0 = 0; k0 < DD; k0 += 16) {
        __syncthreads();
        As[lc*4+0][lr] = apre.x; As[lc*4+1][lr] = apre.y;
        As[lc*4+2][lr] = apre.z; As[lc*4+3][lr] = apre.w;
        Ws[lc*4+0][lr] = wpre.x; Ws[lc*4+1][lr] = wpre.y;
        Ws[lc*4+2][lr] = wpre.z; Ws[lc*4+3][lr] = wpre.w;
        __syncthreads();

        if (k0 + 16 < DD) {
            apre = *(const float4*)(Arow + k0 + 16);
            wpre = *(const float4*)(Wrow + k0 + 16);
        }

#pragma unroll
        for (int kk = 0; kk < 16; kk++) {
            float4 av = *(const float4*)&As[kk][ty * 4];
            ulonglong2 wv = *(const ulonglong2*)&Ws[kk][tx * 4];
            ull aa;
            PACK2(aa, av.x);
            FMA2(acc[0][0], aa, wv.x); FMA2(acc[0][1], aa, wv.y);
            PACK2(aa, av.y);
            FMA2(acc[1][0], aa, wv.x); FMA2(acc[1][1], aa, wv.y);
            PACK2(aa, av.z);
            FMA2(acc[2][0], aa, wv.x); FMA2(acc[2][1], aa, wv.y);
            PACK2(aa, av.w);
            FMA2(acc[3][0], aa, wv.x); FMA2(acc[3][1], aa, wv.y);
        }
    }

    if (is_text) {
        ull b0 = *(const ull*)(bias + n0 + tx * 4);
        ull b1 = *(const ull*)(bias + n0 + tx * 4 + 2);
#pragma unroll
        for (int i = 0; i < 4; i++) { ADD2(acc[i][0], b0); ADD2(acc[i][1], b1); }
    }

#pragma unroll
    for (int i = 0; i < 4; i++) {
        ulonglong2 o;
        o.x = acc[i][0]; o.y = acc[i][1];
        *(ulonglong2*)(C + (size_t)(ty * 4 + i) * VV + n0 + tx * 4) = o;
    }

    // Length tail: outputs 1 and 2 flattened after logits, as float32.
    if (blockIdx.x == 0 && by == 0 && tid < 8) {
        size_t base = (size_t)BB * TT_ * UU * VV;
        if (tid < 4) out[base + tid] = (float)slen[tid];
        else         out[base + tid] = (float)tlen[tid - 4];
    }
}

// ---------------------------------------------------------------------------
// Kernel 2: broadcast add: out[bt, u, v] = sp[bt, v] + tp[b*U + u, v].
// One block per (b,t) row; 128 threads; each thread owns 4 consecutive v.
// Pure DRAM-write-bound streaming; sp/tp stay L2-resident (5 MB << 126 MB).
// (Proven at ~88 us in R2 — the HBM write floor.)
// ---------------------------------------------------------------------------
__global__ __launch_bounds__(128)
void bcast_add_kernel(float* __restrict__ out)
{
    const int bt  = blockIdx.x;           // 0..2047
    const int b   = bt >> 9;              // bt / T
    const int tid = threadIdx.x;          // 0..127 -> v4 index

    const float4* sp4 = (const float4*)g_sp;
    const float4* tp4 = (const float4*)g_tp;

    float4 s = sp4[(size_t)bt * 128 + tid];

    const float4* tprow = tp4 + (size_t)b * UU * 128 + tid;
    float4* ob = (float4*)out + (size_t)bt * UU * 128 + tid;

#pragma unroll 4
    for (int u = 0; u < UU; u++) {
        float4 t = tprow[(size_t)u * 128];
        float4 r;
        r.x = s.x + t.x;
        r.y = s.y + t.y;
        r.z = s.z + t.z;
        r.w = s.w + t.w;
        ob[(size_t)u * 128] = r;
    }
}

extern "C" void kernel_launch(void* const* d_in, const int* in_sizes, int n_in,
                              void* d_out, int out_size)
{
    const float* speech = (const float*)d_in[0];
    const float* text   = (const float*)d_in[1];
    const float* Wm     = (const float*)d_in[2];
    const float* bias   = (const float*)d_in[3];
    const int*   slen   = (const int*)d_in[4];
    const int*   tlen   = (const int*)d_in[5];

    // Phase 1: both projections (speech + text w/ bias) + length tail
    joint_gemm_kernel<<<dim3(8, 40), 256>>>(speech, text, Wm, bias,
                                            slen, tlen, (float*)d_out);

    // Phase 2: broadcast add (DRAM-write-bound floor)
    bcast_add_kernel<<<MS, 128>>>((float*)d_out);
}